// round 17
// baseline (speedup 1.0000x reference)
#include <cuda_runtime.h>
#include <cuda_fp16.h>
#include <cstdint>

#define NN 100000
#define HH 128
#define EE 1600000
#define LN_EPS 1e-5f
#define NB 391           // (NN+255)/256
#define GB64 1563        // (NN+63)/64 gemm tiles

// ---------------- device scratch ----------------
__device__ float  g_x  [NN * HH];    // fp32 master (residual path, row-local)
__device__ __half g_x16[NN * HH];    // fp16 mirror of encoder output (gemm0 A input)
__device__ __half g_hA [NN * HH];    // message buffers (ping-pong; fixes in-place race)
__device__ __half g_hB [NN * HH];
__device__ __half g_P16[NN * HH];    // P = x@W1[:128], fp16 storage
__device__ float  g_Q  [NN * HH];    // Q = x@W1[128:], fp32
__device__ int   g_deg   [NN];
__device__ float g_dinv  [NN];
__device__ int   g_rowptr[NN];
__device__ int   g_cursor[NN];
__device__ int   g_csrc  [EE];
__device__ int   g_eid   [EE];
__device__ int   g_bsum  [NB];
__device__ int   g_boff  [NB];
__device__ __half g_W16[5 * 16384];  // B = W^T, [n][k] row-major, fp16

// ---------------- helpers ----------------
__device__ __forceinline__ uint32_t smem_u32(const void* p) {
    uint32_t a;
    asm("{ .reg .u64 t; cvta.to.shared.u64 t, %1; cvt.u32.u64 %0, t; }" : "=r"(a) : "l"(p));
    return a;
}
__device__ __forceinline__ void ldm4(uint32_t* r, uint32_t addr) {
    asm volatile("ldmatrix.sync.aligned.m8n8.x4.shared.b16 {%0,%1,%2,%3}, [%4];"
                 : "=r"(r[0]), "=r"(r[1]), "=r"(r[2]), "=r"(r[3]) : "r"(addr));
}
__device__ __forceinline__ void mma_f16(float* d, const uint32_t* a, const uint32_t* b) {
    asm volatile("mma.sync.aligned.m16n8k16.row.col.f32.f16.f16.f32 "
                 "{%0,%1,%2,%3}, {%4,%5,%6,%7}, {%8,%9}, {%0,%1,%2,%3};"
                 : "+f"(d[0]), "+f"(d[1]), "+f"(d[2]), "+f"(d[3])
                 : "r"(a[0]), "r"(a[1]), "r"(a[2]), "r"(a[3]), "r"(b[0]), "r"(b[1]));
}

// ---------------- degree ----------------
__global__ void k_deg_zero() {
    int i = blockIdx.x * blockDim.x + threadIdx.x;
    if (i < NN) g_deg[i] = 0;
}
__global__ void k_deg_count(const int* __restrict__ dst) {
    int i = blockIdx.x * blockDim.x + threadIdx.x;
    if (i < EE) atomicAdd(&g_deg[dst[i]], 1);
}

// ---------------- CSR build ----------------
__global__ void k_scanA() {
    __shared__ int ws[8];
    int i = blockIdx.x * 256 + threadIdx.x;
    int v = (i < NN) ? g_deg[i] : 0;
#pragma unroll
    for (int off = 16; off > 0; off >>= 1) v += __shfl_xor_sync(0xffffffffu, v, off);
    if ((threadIdx.x & 31) == 0) ws[threadIdx.x >> 5] = v;
    __syncthreads();
    if (threadIdx.x == 0) {
        int t = 0;
#pragma unroll
        for (int w = 0; w < 8; w++) t += ws[w];
        g_bsum[blockIdx.x] = t;
    }
}
__global__ void k_scanB() {
    __shared__ int s[512];
    int tid = threadIdx.x;
    int v = (tid < NB) ? g_bsum[tid] : 0;
    s[tid] = v;
    __syncthreads();
    for (int off = 1; off < 512; off <<= 1) {
        int t = (tid >= off) ? s[tid - off] : 0;
        __syncthreads();
        s[tid] += t;
        __syncthreads();
    }
    if (tid < NB) g_boff[tid] = s[tid] - v;
}
__global__ void k_scanC() {   // also computes dinv
    __shared__ int s[256];
    int tid = threadIdx.x;
    int i = blockIdx.x * 256 + tid;
    int v = (i < NN) ? g_deg[i] : 0;
    s[tid] = v;
    __syncthreads();
    for (int off = 1; off < 256; off <<= 1) {
        int t = (tid >= off) ? s[tid - off] : 0;
        __syncthreads();
        s[tid] += t;
        __syncthreads();
    }
    if (i < NN) {
        int r = g_boff[blockIdx.x] + s[tid] - v;
        g_rowptr[i] = r;
        g_cursor[i] = r;
        g_dinv[i] = rsqrtf((float)(v + 1));
    }
}
__global__ void k_fill(const int* __restrict__ src, const int* __restrict__ dst) {
    int e = blockIdx.x * blockDim.x + threadIdx.x;
    if (e >= EE) return;
    int d = dst[e];
    int p = atomicAdd(&g_cursor[d], 1);
    g_csrc[p] = src[e];
    g_eid[p] = e;
}

// ---------------- weight prep: transpose + fp16, [n][k] layout ----------------
__global__ void k_prep_w(const float* __restrict__ conv_w, const float* __restrict__ mlp_w1) {
    int mat = blockIdx.x;   // 0..2 conv, 3..4 mlp halves
    const float* W = (mat < 3) ? conv_w + mat * 16384 : mlp_w1 + (mat - 3) * 16384;
    for (int idx = threadIdx.x; idx < 16384; idx += blockDim.x) {
        int n = idx >> 7, k = idx & 127;
        g_W16[mat * 16384 + idx] = __float2half_rn(W[k * 128 + n]);   // B[n][k] = W[k][n]
    }
}

// ---------------- shared GEMM pieces: 64-row A tile, 128-col B, fp16, fp32 acc ----------------
#define RS 272
#define SM_A 0
#define SM_B (64 * RS)
#define SMEM_SZ (192 * RS)   // 52224 B -> 3 CTA/SM

__device__ __forceinline__ void gemm_fill_A(char* smem, const __half* __restrict__ A16,
                                            int row0, int M, int wid, int lane) {
#pragma unroll
    for (int it = 0; it < 8; it++) {
        int r = it * 8 + wid;
        int grow = row0 + r;
        uint2 v = make_uint2(0u, 0u);
        if (grow < M) v = *(const uint2*)&A16[(size_t)grow * 128 + lane * 4];
        *(uint2*)(smem + SM_A + r * RS + lane * 8) = v;
    }
}

__device__ __forceinline__ void gemm_fill_B(char* smem, int mat, int tid) {
    const float4* b = (const float4*)(g_W16 + mat * 16384);
    // 16384 halves = 2048 float4; each [n] row = 128 halves = 16 segs of 16B
#pragma unroll
    for (int i = tid; i < 2048; i += 256) {
        int n = i >> 4, seg = i & 15;
        *(float4*)(smem + SM_B + n * RS + seg * 16) = b[i];
    }
}

template <bool H16>
__device__ __forceinline__ void gemm_core_epi(char* smem, uint32_t sb,
                                              void* __restrict__ Cp, int M,
                                              const float* __restrict__ rowscale,
                                              int row0, int wid, int lane) {
    // warp = 16 rows x 64 cols
    int arow = (wid >> 1) * 16 + (lane & 7) + ((lane >> 3) & 1) * 8;
    uint32_t akb = ((lane >> 4) & 1) * 16;
    uint32_t aA0 = sb + SM_A + arow * RS + akb;
    int brow = (lane & 7) + ((lane >> 4) & 1) * 8;
    uint32_t bkb = ((lane >> 3) & 1) * 16;
    uint32_t bB0 = sb + SM_B + ((wid & 1) * 64 + brow) * RS + bkb;

    float acc[8][4];
#pragma unroll
    for (int n = 0; n < 8; n++)
#pragma unroll
        for (int j = 0; j < 4; j++) acc[n][j] = 0.f;

#pragma unroll
    for (int ks = 0; ks < 8; ks++) {
        uint32_t ko = ks * 32;
        uint32_t a[4];
        ldm4(a, aA0 + ko);
#pragma unroll
        for (int g = 0; g < 4; g++) {
            uint32_t b[4];
            ldm4(b, bB0 + g * 16 * RS + ko);
            mma_f16(acc[g * 2 + 0], a, &b[0]);
            mma_f16(acc[g * 2 + 1], a, &b[2]);
        }
    }

    int r0r = row0 + (wid >> 1) * 16 + (lane >> 2);
    int r1r = r0r + 8;
    int cbase = (wid & 1) * 64;
    float s0 = 1.f, s1 = 1.f;
    if (rowscale) {
        if (r0r < M) s0 = rowscale[r0r];
        if (r1r < M) s1 = rowscale[r1r];
    }
#pragma unroll
    for (int n = 0; n < 8; n++) {
        int col = cbase + n * 8 + (lane & 3) * 2;
        if (H16) {
            __half2* C2 = (__half2*)Cp;
            if (r0r < M)
                C2[(size_t)r0r * 64 + (col >> 1)] = __floats2half2_rn(acc[n][0] * s0, acc[n][1] * s0);
            if (r1r < M)
                C2[(size_t)r1r * 64 + (col >> 1)] = __floats2half2_rn(acc[n][2] * s1, acc[n][3] * s1);
        } else {
            float* C = (float*)Cp;
            if (r0r < M) {
                float2 o = {acc[n][0] * s0, acc[n][1] * s0};
                *(float2*)&C[(size_t)r0r * 128 + col] = o;
            }
            if (r1r < M) {
                float2 o = {acc[n][2] * s1, acc[n][3] * s1};
                *(float2*)&C[(size_t)r1r * 128 + col] = o;
            }
        }
    }
}

// first-layer GEMM: reads encoder's fp16 x-mirror, writes scaled h (buffer A)
__global__ void __launch_bounds__(256, 3)
k_gemm_h16(const __half* __restrict__ A16, int mat, __half* __restrict__ C, int M,
           const float* __restrict__ rowscale) {
    extern __shared__ char smem[];
    uint32_t sb = smem_u32(smem);
    int tid = threadIdx.x, wid = tid >> 5, lane = tid & 31;
    int row0 = blockIdx.x * 64;
    gemm_fill_B(smem, mat, tid);
    gemm_fill_A(smem, A16, row0, M, wid, lane);
    __syncthreads();
    gemm_core_epi<true>(smem, sb, C, M, rowscale, row0, wid, lane);
}

// ---------------- gather one node (warp-collective) ----------------
__device__ __forceinline__ void acc_h16(const __half* __restrict__ hin,
                                        float* a, int row, int lane) {
    uint2 hv = *(const uint2*)&hin[(size_t)row * 128 + lane * 4];
    float2 fa = __half22float2(*(__half2*)&hv.x);
    float2 fb = __half22float2(*(__half2*)&hv.y);
    a[0] += fa.x; a[1] += fa.y; a[2] += fb.x; a[3] += fb.y;
}

__device__ __forceinline__ float4 gather_node(const __half* __restrict__ hin,
                                              int n, int lane,
                                              const float4 b4, const float4 lg4, const float4 lb4) {
    int beg = g_rowptr[n];
    int cnt = g_deg[n];

    float acc[4] = {0.f, 0.f, 0.f, 0.f};
    acc_h16(hin, acc, n, lane);                    // self loop (pre-scaled)

    for (int base = 0; base < cnt; base += 32) {
        int k = cnt - base;
        if (k > 32) k = 32;
        int sidx = (lane < k) ? g_csrc[beg + base + lane] : 0;
        int j = 0;
        for (; j + 8 <= k; j += 8) {
            int s0 = __shfl_sync(0xffffffffu, sidx, j + 0);
            int s1 = __shfl_sync(0xffffffffu, sidx, j + 1);
            int s2 = __shfl_sync(0xffffffffu, sidx, j + 2);
            int s3 = __shfl_sync(0xffffffffu, sidx, j + 3);
            int s4 = __shfl_sync(0xffffffffu, sidx, j + 4);
            int s5 = __shfl_sync(0xffffffffu, sidx, j + 5);
            int s6 = __shfl_sync(0xffffffffu, sidx, j + 6);
            int s7 = __shfl_sync(0xffffffffu, sidx, j + 7);
            acc_h16(hin, acc, s0, lane); acc_h16(hin, acc, s1, lane);
            acc_h16(hin, acc, s2, lane); acc_h16(hin, acc, s3, lane);
            acc_h16(hin, acc, s4, lane); acc_h16(hin, acc, s5, lane);
            acc_h16(hin, acc, s6, lane); acc_h16(hin, acc, s7, lane);
        }
        for (; j < k; j++) {
            int sj = __shfl_sync(0xffffffffu, sidx, j);
            acc_h16(hin, acc, sj, lane);
        }
    }

    float di = g_dinv[n];
    float v[4] = {acc[0] * di + b4.x, acc[1] * di + b4.y,
                  acc[2] * di + b4.z, acc[3] * di + b4.w};

    float s = 0.f, ss = 0.f;
#pragma unroll
    for (int j = 0; j < 4; j++) { s += v[j]; ss += v[j] * v[j]; }
#pragma unroll
    for (int off = 16; off > 0; off >>= 1) {
        s  += __shfl_xor_sync(0xffffffffu, s,  off);
        ss += __shfl_xor_sync(0xffffffffu, ss, off);
    }
    float mu   = s * (1.f / HH);
    float var  = ss * (1.f / HH) - mu * mu;
    float linv = rsqrtf(var + LN_EPS);

    float4 xo = *(const float4*)&g_x[(size_t)n * 128 + lane * 4];
    float4 y;
    y.x = fmaxf((v[0] - mu) * linv * lg4.x + lb4.x, 0.f) + xo.x;
    y.y = fmaxf((v[1] - mu) * linv * lg4.y + lb4.y, 0.f) + xo.y;
    y.z = fmaxf((v[2] - mu) * linv * lg4.z + lb4.z, 0.f) + xo.z;
    y.w = fmaxf((v[3] - mu) * linv * lg4.w + lb4.w, 0.f) + xo.w;
    return y;
}

// gather phase: reads hin (prev layer), deposits fp16 rows into smem A tile, updates g_x
__device__ __forceinline__ void gather_phase(char* smem, const __half* __restrict__ hin,
                                             int row0,
                                             const float* __restrict__ cb,
                                             const float* __restrict__ lg,
                                             const float* __restrict__ lb,
                                             float* __restrict__ xdst,
                                             int wid, int lane) {
    float4 b4  = *(const float4*)&cb[lane * 4];
    float4 lg4 = *(const float4*)&lg[lane * 4];
    float4 lb4 = *(const float4*)&lb[lane * 4];
#pragma unroll 1
    for (int i = 0; i < 8; i++) {
        int r = wid * 8 + i;
        int n = row0 + r;
        uint2 av = make_uint2(0u, 0u);
        if (n < NN) {
            float4 y = gather_node(hin, n, lane, b4, lg4, lb4);
            *(float4*)&xdst[(size_t)n * 128 + lane * 4] = y;
            __half2 m0 = __floats2half2_rn(y.x, y.y);
            __half2 m1 = __floats2half2_rn(y.z, y.w);
            av.x = *(uint32_t*)&m0;
            av.y = *(uint32_t*)&m1;
        }
        *(uint2*)(smem + SM_A + r * RS + lane * 8) = av;
    }
}

// fused: gather(hin) + GEMM(W[mat]) -> scaled hout (distinct buffer, no race)
__global__ void __launch_bounds__(256, 3)
k_layer(int mat, const __half* __restrict__ hin, __half* __restrict__ hout,
        const float* __restrict__ cb,
        const float* __restrict__ lg, const float* __restrict__ lb) {
    extern __shared__ char smem[];
    uint32_t sb = smem_u32(smem);
    int tid = threadIdx.x, wid = tid >> 5, lane = tid & 31;
    int row0 = blockIdx.x * 64;
    gemm_fill_B(smem, mat, tid);
    gather_phase(smem, hin, row0, cb, lg, lb, g_x, wid, lane);
    __syncthreads();
    gemm_core_epi<true>(smem, sb, hout, NN, g_dinv, row0, wid, lane);
}

// fused final: gather(hin) -> out, then P (fp16) and Q (fp32)
__global__ void __launch_bounds__(256, 3)
k_layer_pq(const __half* __restrict__ hin,
           const float* __restrict__ cb,
           const float* __restrict__ lg, const float* __restrict__ lb,
           float* __restrict__ xout) {
    extern __shared__ char smem[];
    uint32_t sb = smem_u32(smem);
    int tid = threadIdx.x, wid = tid >> 5, lane = tid & 31;
    int row0 = blockIdx.x * 64;
    gemm_fill_B(smem, 3, tid);
    gather_phase(smem, hin, row0, cb, lg, lb, xout, wid, lane);
    __syncthreads();
    gemm_core_epi<true>(smem, sb, g_P16, NN, nullptr, row0, wid, lane);
    __syncthreads();
    gemm_fill_B(smem, 4, tid);
    __syncthreads();
    gemm_core_epi<false>(smem, sb, g_Q, NN, nullptr, row0, wid, lane);
}

// ---------------- encoder: writes fp32 x + fp16 mirror ----------------
__global__ void k_encoder(const float* __restrict__ nf,
                          const float* __restrict__ w,  const float* __restrict__ b,
                          const float* __restrict__ lg, const float* __restrict__ lb) {
    int gw = blockIdx.x * 8 + (threadIdx.x >> 5);
    int nw = gridDim.x * 8;
    int lane = threadIdx.x & 31;

    float wr[7][4], br[4], lgr[4], lbr[4];
#pragma unroll
    for (int j = 0; j < 4; j++) {
        int c = lane + 32 * j;
        br[j] = b[c]; lgr[j] = lg[c]; lbr[j] = lb[c];
#pragma unroll
        for (int k = 0; k < 7; k++) wr[k][j] = w[k * HH + c];
    }

    for (int n = gw; n < NN; n += nw) {
        float f[7];
#pragma unroll
        for (int k = 0; k < 7; k++) f[k] = nf[n * 7 + k];

        float v[4];
#pragma unroll
        for (int j = 0; j < 4; j++) {
            float a = br[j];
#pragma unroll
            for (int k = 0; k < 7; k++) a = fmaf(f[k], wr[k][j], a);
            v[j] = a;
        }
        float s = 0.f, ss = 0.f;
#pragma unroll
        for (int j = 0; j < 4; j++) { s += v[j]; ss += v[j] * v[j]; }
#pragma unroll
        for (int off = 16; off > 0; off >>= 1) {
            s  += __shfl_xor_sync(0xffffffffu, s,  off);
            ss += __shfl_xor_sync(0xffffffffu, ss, off);
        }
        float mu  = s * (1.f / HH);
        float var = ss * (1.f / HH) - mu * mu;
        float inv = rsqrtf(var + LN_EPS);
#pragma unroll
        for (int j = 0; j < 4; j++) {
            int c = lane + 32 * j;
            float y = fmaxf((v[j] - mu) * inv * lgr[j] + lbr[j], 0.f);
            g_x  [(size_t)n * HH + c] = y;
            g_x16[(size_t)n * HH + c] = __float2half_rn(y);
        }
    }
}

// ---------------- edge MLP, CSR-grouped, smem-transpose reduction ----------------
__global__ void __launch_bounds__(256)
k_edge_mlp_csr(const float* __restrict__ b1, const float* __restrict__ w2,
               const float* __restrict__ b2, float* __restrict__ out) {
    __shared__ float sp[8][32][33];
    int wslot = threadIdx.x >> 5;
    int n = blockIdx.x * 8 + wslot;
    if (n >= NN) return;
    int lane = threadIdx.x & 31;

    int beg = g_rowptr[n];
    int cnt = g_deg[n];
    if (cnt == 0) return;

    float4 qb = *(const float4*)&g_Q[(size_t)n * 128 + lane * 4];
    float4 bb = *(const float4*)&b1[lane * 4];
    qb.x += bb.x; qb.y += bb.y; qb.z += bb.z; qb.w += bb.w;
    float4 w = *(const float4*)&w2[lane * 4];
    float bias2 = b2[0];

    for (int base = 0; base < cnt; base += 32) {
        int k = cnt - base;
        if (k > 32) k = 32;
        int sidx = 0, eidx = 0;
        if (lane < k) {
            sidx = g_csrc[beg + base + lane];
            eidx = g_eid [beg + base + lane];
        }
        for (int j = 0; j < k; j++) {
            int sj = __shfl_sync(0xffffffffu, sidx, j);
            uint2 pv = *(const uint2*)&g_P16[(size_t)sj * 128 + lane * 4];
            float2 pa = __half22float2(*(__half2*)&pv.x);
            float2 pb = __half22float2(*(__half2*)&pv.y);
            float h0 = fmaxf(pa.x + qb.x, 0.f);
            float h1 = fmaxf(pa.y + qb.y, 0.f);
            float h2 = fmaxf(pb.x + qb.z, 0.f);
            float h3 = fmaxf(pb.y + qb.w, 0.f);
            sp[wslot][j][lane] = fmaf(h0, w.x, fmaf(h1, w.y, fmaf(h2, w.z, h3 * w.w)));
        }
        __syncwarp();
        if (lane < k) {
            const float* row = sp[wslot][lane];   // 4B-aligned; scalar loads
            float t0 = 0.f, t1 = 0.f, t2 = 0.f, t3 = 0.f;
#pragma unroll
            for (int i = 0; i < 32; i += 4) {
                t0 += row[i + 0];
                t1 += row[i + 1];
                t2 += row[i + 2];
                t3 += row[i + 3];
            }
            out[eidx] = (t0 + t1) + (t2 + t3) + bias2;
        }
        __syncwarp();
    }
}

// ---------------- host ----------------
extern "C" void kernel_launch(void* const* d_in, const int* in_sizes, int n_in,
                              void* d_out, int out_size) {
    const float* nf       = (const float*)d_in[0];
    const int*   ei       = (const int*)  d_in[1];
    const float* enc_w    = (const float*)d_in[3];
    const float* enc_b    = (const float*)d_in[4];
    const float* enc_ln_g = (const float*)d_in[5];
    const float* enc_ln_b = (const float*)d_in[6];
    const float* conv_w   = (const float*)d_in[7];
    const float* conv_b   = (const float*)d_in[8];
    const float* ln_g     = (const float*)d_in[9];
    const float* ln_b     = (const float*)d_in[10];
    const float* mlp_w1   = (const float*)d_in[11];
    const float* mlp_b1   = (const float*)d_in[12];
    const float* mlp_w2   = (const float*)d_in[13];
    const float* mlp_b2   = (const float*)d_in[14];

    const int* src = ei;
    const int* dst = ei + EE;

    float* out        = (float*)d_out;
    float* out_logits = out + (size_t)NN * HH;

    float *pdinv;
    __half *px16, *phA, *phB;
    cudaGetSymbolAddress((void**)&px16, g_x16);
    cudaGetSymbolAddress((void**)&phA,  g_hA);
    cudaGetSymbolAddress((void**)&phB,  g_hB);
    cudaGetSymbolAddress((void**)&pdinv, g_dinv);

    cudaFuncSetAttribute(k_gemm_h16,  cudaFuncAttributeMaxDynamicSharedMemorySize, SMEM_SZ);
    cudaFuncSetAttribute(k_layer,     cudaFuncAttributeMaxDynamicSharedMemorySize, SMEM_SZ);
    cudaFuncSetAttribute(k_layer_pq,  cudaFuncAttributeMaxDynamicSharedMemorySize, SMEM_SZ);

    // side stream + events (created once; host-side only)
    static cudaStream_t s1 = nullptr;
    static cudaEvent_t ev_fork0 = nullptr, ev_enc = nullptr, ev_fork1 = nullptr, ev_fill = nullptr;
    if (!s1) {
        cudaStreamCreateWithFlags(&s1, cudaStreamNonBlocking);
        cudaEventCreateWithFlags(&ev_fork0, cudaEventDisableTiming);
        cudaEventCreateWithFlags(&ev_enc,   cudaEventDisableTiming);
        cudaEventCreateWithFlags(&ev_fork1, cudaEventDisableTiming);
        cudaEventCreateWithFlags(&ev_fill,  cudaEventDisableTiming);
    }

    // ---- fork: encoder + weight prep on s1 ----
    cudaEventRecord(ev_fork0, 0);
    cudaStreamWaitEvent(s1, ev_fork0, 0);
    k_encoder<<<1184, 256, 0, s1>>>(nf, enc_w, enc_b, enc_ln_g, enc_ln_b);
    k_prep_w <<<5, 256, 0, s1>>>(conv_w, mlp_w1);
    cudaEventRecord(ev_enc, s1);

    // ---- main: degree + scan chain ----
    k_deg_zero <<<(NN + 255) / 256, 256>>>();
    k_deg_count<<<(EE + 255) / 256, 256>>>(dst);
    k_scanA<<<NB, 256>>>();
    k_scanB<<<1, 512>>>();
    k_scanC<<<NB, 256>>>();

    // ---- fork: fill runs under gemm0 ----
    cudaEventRecord(ev_fork1, 0);
    cudaStreamWaitEvent(s1, ev_fork1, 0);
    k_fill<<<(EE + 255) / 256, 256, 0, s1>>>(src, dst);
    cudaEventRecord(ev_fill, s1);

    // ---- main: fused layer pipeline (h ping-pongs A -> B -> A) ----
    cudaStreamWaitEvent(0, ev_enc, 0);
    k_gemm_h16<<<GB64, 256, SMEM_SZ>>>(px16, 0, phA, NN, pdinv);   // h0 -> A
    cudaStreamWaitEvent(0, ev_fill, 0);
    k_layer   <<<GB64, 256, SMEM_SZ>>>(1, phA, phB, conv_b,          ln_g,          ln_b);
    k_layer   <<<GB64, 256, SMEM_SZ>>>(2, phB, phA, conv_b + HH,     ln_g + HH,     ln_b + HH);
    k_layer_pq<<<GB64, 256, SMEM_SZ>>>(   phA,      conv_b + 2 * HH, ln_g + 2 * HH, ln_b + 2 * HH, out);
    k_edge_mlp_csr<<<(NN + 7) / 8, 256>>>(mlp_b1, mlp_w2, mlp_b2, out_logits);
}